// round 8
// baseline (speedup 1.0000x reference)
#include <cuda_runtime.h>
#include <cuda_bf16.h>
#include <cstdint>

#define BH    32
#define NSEQ  4096
#define DDIM  64
#define MFEAT 266
#define MP    320
#define NT    32
#define KSPL  16
#define KSEG  (NSEQ / KSPL)

#define DNORM   0.35355339059327373f
#define RATIO_C 0.061313933948496576f
#define REPS_C  6.1313933948496576e-06f   // ratio * 1e-4
#define NEGINF  -1.0e30f

// ---------------- global scratch (static; no cudaMalloc) --------------------
__device__ float        g_ctxS[(size_t)KSPL * BH * 72 * MP];   // K-split ctx^T partials
__device__ float        g_ctxM[KSPL * BH * 2];                 // per-slab stabilizer max
__device__ float        g_ctxsum[BH * 72];                     // sum_m ctx[m,e] (incl ksum at e=64)
__device__ uint32_t     g_cthp[(size_t)BH * 72 * 160];         // ctx^T hi bf16 pairs
__device__ uint32_t     g_ctlp[(size_t)BH * 72 * 160];         // ctx^T lo bf16 pairs
__device__ unsigned int g_kmax_enc;

__device__ __forceinline__ unsigned int enc_f(float f) {
    unsigned int u = __float_as_uint(f);
    return (u & 0x80000000u) ? ~u : (u | 0x80000000u);
}
__device__ __forceinline__ float dec_f(unsigned int k) {
    return (k & 0x80000000u) ? __uint_as_float(k & 0x7fffffffu) : __uint_as_float(~k);
}
__device__ __forceinline__ uint32_t smem_u32(const void* p) {
    uint32_t a;
    asm("{ .reg .u64 t; cvta.to.shared.u64 t, %1; cvt.u32.u64 %0, t; }" : "=r"(a) : "l"(p));
    return a;
}
__device__ __forceinline__ uint32_t packbf(float a, float b) {
    __nv_bfloat162 t = __floats2bfloat162_rn(a, b);
    return reinterpret_cast<uint32_t&>(t);
}
__device__ __forceinline__ void split2(float a, float b, uint32_t& hi, uint32_t& lo) {
    __nv_bfloat16 ha = __float2bfloat16_rn(a), hb = __float2bfloat16_rn(b);
    float ra = a - __bfloat162float(ha), rb = b - __bfloat162float(hb);
    __nv_bfloat162 H; H.x = ha; H.y = hb;
    hi = reinterpret_cast<uint32_t&>(H);
    lo = packbf(ra, rb);
}

// ---------------- mma.sync + ldmatrix helpers -------------------------------
__device__ __forceinline__ void ldsm_x4(uint32_t* r, uint32_t addr) {
    asm volatile("ldmatrix.sync.aligned.m8n8.x4.shared.b16 {%0,%1,%2,%3}, [%4];"
        : "=r"(r[0]), "=r"(r[1]), "=r"(r[2]), "=r"(r[3]) : "r"(addr));
}
__device__ __forceinline__ void ldsm_x2(uint32_t* r, uint32_t addr) {
    asm volatile("ldmatrix.sync.aligned.m8n8.x2.shared.b16 {%0,%1}, [%2];"
        : "=r"(r[0]), "=r"(r[1]) : "r"(addr));
}
__device__ __forceinline__ void ldsm_x4t(uint32_t* r, uint32_t addr) {
    asm volatile("ldmatrix.sync.aligned.m8n8.x4.trans.shared.b16 {%0,%1,%2,%3}, [%4];"
        : "=r"(r[0]), "=r"(r[1]), "=r"(r[2]), "=r"(r[3]) : "r"(addr));
}
__device__ __forceinline__ void ldsm_x2t(uint32_t* r, uint32_t addr) {
    asm volatile("ldmatrix.sync.aligned.m8n8.x2.trans.shared.b16 {%0,%1}, [%2];"
        : "=r"(r[0]), "=r"(r[1]) : "r"(addr));
}
__device__ __forceinline__ void mma_bf16(float* c, const uint32_t* a, const uint32_t* b) {
    asm volatile("mma.sync.aligned.m16n8k16.row.col.f32.bf16.bf16.f32 "
        "{%0,%1,%2,%3}, {%4,%5,%6,%7}, {%8,%9}, {%0,%1,%2,%3};"
        : "+f"(c[0]), "+f"(c[1]), "+f"(c[2]), "+f"(c[3])
        : "r"(a[0]), "r"(a[1]), "r"(a[2]), "r"(a[3]), "r"(b[0]), "r"(b[1]));
}

// ---------------------------------------------------------------------------
__global__ void init_kernel() {
    if (threadIdx.x == 0 && blockIdx.x == 0) g_kmax_enc = 0u;
}

// ---------------------------------------------------------------------------
// ctx_fused (online): per chunk of 64 rows: dd (3-term GEMM) -> chunk max ->
// rescale accC -> kp = ratio*exp(dd - diag - M) (NO eps; eps analytic) ->
// kp^T @ [v|1] GEMM. ones-column at m=266 gives vsum (exempt from rescale).
// grid (2*KSPL, BH), block 320.
// ---------------------------------------------------------------------------
#define CP_H 0
#define CP_L 23040
#define CK_H 46080
#define CK_L 55296
#define CT_H 64512
#define CT_L 86016
#define CW_H 107520
#define CW_L 118784
#define CD_  130048
#define C_MX 130304
#define CX_SZ 130368

__global__ void __launch_bounds__(320) ctx_fused(const float* __restrict__ k_in,
                                                 const float* __restrict__ v_in,
                                                 const float* __restrict__ proj) {
    extern __shared__ char smem[];
    uint32_t sb = smem_u32(smem);
    int tid = threadIdx.x, w = tid >> 5, lane = tid & 31;
    int bh = blockIdx.y, mhalf = blockIdx.x & 1, ks = blockIdx.x >> 1;

    // stage proj half [160 m rows x 64 k] hi/lo
    for (int i = tid; i < 160 * 32; i += 320) {
        int r = i >> 5, p = i & 31;
        int m = mhalf * 160 + r;
        float2 v = (m < MFEAT) ? *(const float2*)(proj + m * 64 + 2 * p) : make_float2(0.f, 0.f);
        uint32_t hi, lo; split2(v.x, v.y, hi, lo);
        *(uint32_t*)(smem + CP_H + r * 144 + 4 * p) = hi;
        *(uint32_t*)(smem + CP_L + r * 144 + 4 * p) = lo;
    }

    float accC[9][4];
    #pragma unroll
    for (int n = 0; n < 9; n++)
        #pragma unroll
        for (int x = 0; x < 4; x++) accC[n][x] = 0.f;
    float Mold = NEGINF;

    int wc5 = w % 5, mg2 = w / 5;

    #pragma unroll 1
    for (int c = 0; c < KSEG / 64; c++) {
        int n0 = ks * KSEG + c * 64;
        __syncthreads();
        const float* kb = k_in + ((size_t)bh * NSEQ + n0) * DDIM;
        for (int i = tid; i < 64 * 32; i += 320) {
            int r = i >> 5, p = i & 31;
            float2 v = *(const float2*)(kb + r * 64 + 2 * p);
            uint32_t hi, lo; split2(DNORM * v.x, DNORM * v.y, hi, lo);
            *(uint32_t*)(smem + CK_H + r * 144 + 4 * p) = hi;
            *(uint32_t*)(smem + CK_L + r * 144 + 4 * p) = lo;
        }
        const float* vb = v_in + ((size_t)bh * NSEQ + n0) * DDIM;
        for (int i = tid; i < 64 * 36; i += 320) {
            int r = i / 36, p = i % 36;
            int e = 2 * p;
            float2 wv;
            if (e < 64)       wv = *(const float2*)(vb + r * 64 + e);
            else if (e == 64) wv = make_float2(1.f, 0.f);
            else              wv = make_float2(0.f, 0.f);
            uint32_t hi, lo; split2(wv.x, wv.y, hi, lo);
            *(uint32_t*)(smem + CW_H + r * 176 + 4 * p) = hi;
            *(uint32_t*)(smem + CW_L + r * 176 + 4 * p) = lo;
        }
        __syncthreads();

        // diag from staged hi+lo (exact to ~2^-17): diag = 0.5 * sum (DN x)^2
        if (tid < 64) {
            float s = 0.f;
            #pragma unroll
            for (int p = 0; p < 32; p++) {
                uint32_t hu = *(uint32_t*)(smem + CK_H + tid * 144 + 4 * p);
                uint32_t lu = *(uint32_t*)(smem + CK_L + tid * 144 + 4 * p);
                __nv_bfloat162 hb = reinterpret_cast<__nv_bfloat162&>(hu);
                __nv_bfloat162 lb = reinterpret_cast<__nv_bfloat162&>(lu);
                float x0 = __bfloat162float(hb.x) + __bfloat162float(lb.x);
                float x1 = __bfloat162float(hb.y) + __bfloat162float(lb.y);
                s += x0 * x0 + x1 * x1;
            }
            ((float*)(smem + CD_))[tid] = 0.5f * s;
        }

        // GEMM1: dd[64 n x 160 m] (3-term). warp: mt pair mg2, cols 32*wc5
        float acc1[2][4][4];
        #pragma unroll
        for (int t = 0; t < 2; t++)
            #pragma unroll
            for (int n = 0; n < 4; n++)
                #pragma unroll
                for (int x = 0; x < 4; x++) acc1[t][n][x] = 0.f;
        #pragma unroll
        for (int kt = 0; kt < 4; kt++) {
            uint32_t ah[2][4], al[2][4];
            int arow = lane & 15, koff = (lane >> 4) * 16;
            #pragma unroll
            for (int t = 0; t < 2; t++) {
                uint32_t a = sb + CK_H + (uint32_t)(16 * (2 * mg2 + t) + arow) * 144 + kt * 32 + koff;
                ldsm_x4(ah[t], a);
                ldsm_x4(al[t], a + (CK_L - CK_H));
            }
            uint32_t bhf[4][2], blf[4][2];
            int brow = lane & 7, bk = ((lane >> 3) & 1) * 16;
            #pragma unroll
            for (int n = 0; n < 4; n++) {
                uint32_t a = sb + CP_H + (uint32_t)(32 * wc5 + 8 * n + brow) * 144 + kt * 32 + bk;
                ldsm_x2(bhf[n], a);
                ldsm_x2(blf[n], a + (CP_L - CP_H));
            }
            #pragma unroll
            for (int t = 0; t < 2; t++)
                #pragma unroll
                for (int n = 0; n < 4; n++) {
                    mma_bf16(acc1[t][n], ah[t], bhf[n]);
                    mma_bf16(acc1[t][n], ah[t], blf[n]);
                    mma_bf16(acc1[t][n], al[t], bhf[n]);
                }
        }
        // chunk max (padding cols give dd=0; harmless, real max >> 0)
        float lm = NEGINF;
        #pragma unroll
        for (int t = 0; t < 2; t++)
            #pragma unroll
            for (int n = 0; n < 4; n++)
                #pragma unroll
                for (int x = 0; x < 4; x++) lm = fmaxf(lm, acc1[t][n][x]);
        #pragma unroll
        for (int off = 16; off; off >>= 1) lm = fmaxf(lm, __shfl_xor_sync(0xffffffffu, lm, off));
        if (lane == 0) ((float*)(smem + C_MX))[w] = lm;
        __syncthreads();
        float bmax = NEGINF;
        #pragma unroll
        for (int i = 0; i < 10; i++) bmax = fmaxf(bmax, ((float*)(smem + C_MX))[i]);
        float Mnew = fmaxf(Mold, bmax);
        float factor = __expf(Mold - Mnew);

        // rescale accC (vsum row m==266 exempt)
        {
            int mg = mhalf * 160 + 16 * w + (lane >> 2);
            float f01 = factor;
            float f23 = (mg + 8 == 266) ? 1.f : factor;
            #pragma unroll
            for (int n = 0; n < 9; n++) {
                accC[n][0] *= f01; accC[n][1] *= f01;
                accC[n][2] *= f23; accC[n][3] *= f23;
            }
        }
        // epilogue: kp = ratio*exp(dd - diag - Mnew); ones col at m=266
        float* dg = (float*)(smem + CD_);
        #pragma unroll
        for (int t = 0; t < 2; t++)
            #pragma unroll
            for (int n = 0; n < 4; n++) {
                int r0 = 16 * (2 * mg2 + t) + (lane >> 2);
                int col = 32 * wc5 + 8 * n + 2 * (lane & 3);
                int gm = mhalf * 160 + col;
                float off0 = dg[r0] + Mnew, off1 = dg[r0 + 8] + Mnew;
                float v0 = (gm < MFEAT) ? RATIO_C * __expf(acc1[t][n][0] - off0) : ((gm == MFEAT) ? 1.f : 0.f);
                float v1 = (gm + 1 < MFEAT) ? RATIO_C * __expf(acc1[t][n][1] - off0) : 0.f;
                float v2 = (gm < MFEAT) ? RATIO_C * __expf(acc1[t][n][2] - off1) : ((gm == MFEAT) ? 1.f : 0.f);
                float v3 = (gm + 1 < MFEAT) ? RATIO_C * __expf(acc1[t][n][3] - off1) : 0.f;
                uint32_t hi, lo;
                split2(v0, v1, hi, lo);
                *(uint32_t*)(smem + CT_H + r0 * 336 + col * 2) = hi;
                *(uint32_t*)(smem + CT_L + r0 * 336 + col * 2) = lo;
                split2(v2, v3, hi, lo);
                *(uint32_t*)(smem + CT_H + (r0 + 8) * 336 + col * 2) = hi;
                *(uint32_t*)(smem + CT_L + (r0 + 8) * 336 + col * 2) = lo;
            }
        Mold = Mnew;
        __syncthreads();

        // GEMM2: C[160 m x 72 e] += kp^T @ w
        #pragma unroll
        for (int kk = 0; kk < 4; kk++) {
            uint32_t ath[4], atl[4];
            int kra = (lane & 7) + 8 * ((lane >> 4) & 1);
            int mhb = ((lane >> 3) & 1) * 16;
            uint32_t a = sb + CT_H + (uint32_t)(kk * 16 + kra) * 336 + 32 * w + mhb;
            ldsm_x4t(ath, a);
            ldsm_x4t(atl, a + (CT_L - CT_H));
            uint32_t bwh[9][2], bwl[9][2];
            int krb = (lane & 7) + 8 * ((lane >> 3) & 1);
            #pragma unroll
            for (int n = 0; n < 9; n++) {
                uint32_t b = sb + CW_H + (uint32_t)(kk * 16 + krb) * 176 + 16 * n;
                ldsm_x2t(bwh[n], b);
                ldsm_x2t(bwl[n], b + (CW_L - CW_H));
            }
            #pragma unroll
            for (int n = 0; n < 9; n++) {
                mma_bf16(accC[n], ath, bwh[n]);
                mma_bf16(accC[n], ath, bwl[n]);
                mma_bf16(accC[n], atl, bwh[n]);
            }
        }
    }

    float* slab = g_ctxS + ((size_t)(ks * BH + bh)) * 72 * MP;
    #pragma unroll
    for (int n = 0; n < 9; n++) {
        int mg = mhalf * 160 + 16 * w + (lane >> 2);
        int e = 8 * n + 2 * (lane & 3);
        slab[(size_t)e * MP + mg]           = accC[n][0];
        slab[(size_t)(e + 1) * MP + mg]     = accC[n][1];
        slab[(size_t)e * MP + mg + 8]       = accC[n][2];
        slab[(size_t)(e + 1) * MP + mg + 8] = accC[n][3];
    }
    if (tid == 0) {
        g_ctxM[(ks * BH + bh) * 2 + mhalf] = Mold;
        atomicMax(&g_kmax_enc, enc_f(Mold));
    }
}

// ---------------------------------------------------------------------------
// convert: merge slabs with e^{M_s - G}; add analytic EPS (ratio*EPS*vsum[e]);
// bf16 split; also reduce ctxsum[e] = sum_{m<266} ctx[m,e].
// grid (72, BH), block 160.
// ---------------------------------------------------------------------------
__global__ void __launch_bounds__(160) convert_kernel() {
    __shared__ float sc[KSPL * 2];
    __shared__ float vs_sh;
    __shared__ float red[5];
    int e = blockIdx.x, bh = blockIdx.y, t = threadIdx.x;
    float G = dec_f(g_kmax_enc);
    if (t < KSPL * 2) sc[t] = __expf(g_ctxM[((t >> 1) * BH + bh) * 2 + (t & 1)] - G);
    if (t == 0) {
        float v = 0.f;
        #pragma unroll
        for (int ks = 0; ks < KSPL; ks++)
            v += g_ctxS[(((size_t)(ks * BH + bh)) * 72 + e) * MP + MFEAT];
        vs_sh = v;
    }
    __syncthreads();

    int mh = (t >= 80) ? 1 : 0;
    float sx = 0.f, sy = 0.f;
    #pragma unroll
    for (int ks = 0; ks < KSPL; ks++) {
        float2 vv = *(const float2*)(g_ctxS + (((size_t)(ks * BH + bh)) * 72 + e) * MP + 2 * t);
        float s = sc[ks * 2 + mh];
        sx += s * vv.x; sy += s * vv.y;
    }
    float eps_add = REPS_C * vs_sh;
    int m0 = 2 * t;
    float fx = (m0     < MFEAT) ? sx + eps_add : 0.f;
    float fy = (m0 + 1 < MFEAT) ? sy + eps_add : 0.f;
    uint32_t hi, lo; split2(fx, fy, hi, lo);
    g_cthp[((size_t)bh * 72 + e) * 160 + t] = hi;
    g_ctlp[((size_t)bh * 72 + e) * 160 + t] = lo;

    float part = fx + fy;
    #pragma unroll
    for (int off = 16; off; off >>= 1) part += __shfl_xor_sync(0xffffffffu, part, off);
    if ((t & 31) == 0) red[t >> 5] = part;
    __syncthreads();
    if (t == 0) g_ctxsum[bh * 72 + e] = red[0] + red[1] + red[2] + red[3] + red[4];
}

// ---------------------------------------------------------------------------
// out_fused (single-pass online): per chunk: dd_q (3-term) -> per-row chunk max
// -> rescale accO -> qp = ratio*exp(dd - diag - M) (no eps) -> GEMM vs ctx.
// End: accO += ratio*EPS*ctxsum[e]; divide by col 64.
// ---------------------------------------------------------------------------
#define OP_H  0
#define OP_L  46080
#define OQ_H  92160
#define OQ_L  110592
#define OS_H  129024
#define OS_L  147456
#define OC_H  165888
#define OC_L  176256
#define O_DG  186624
#define O_RA  187136
#define O_RB  187648
#define O_MPV 188160
#define O_FC  188672
#define O_OFF 189184
#define OS2_SZ 189696

__global__ void __launch_bounds__(256) out_fused(const float* __restrict__ q_in,
                                                 const float* __restrict__ proj,
                                                 float* __restrict__ out) {
    extern __shared__ char smem[];
    uint32_t sb = smem_u32(smem);
    int tid = threadIdx.x, w = tid >> 5, lane = tid & 31;
    int bh = blockIdx.y, nt = blockIdx.x;
    const float* qb = q_in + ((size_t)bh * NSEQ + nt * 128) * DDIM;

    for (int i = tid; i < 128 * 32; i += 256) {
        int r = i >> 5, p = i & 31;
        float2 v = *(const float2*)(qb + r * 64 + 2 * p);
        uint32_t hi, lo; split2(DNORM * v.x, DNORM * v.y, hi, lo);
        *(uint32_t*)(smem + OQ_H + r * 144 + 4 * p) = hi;
        *(uint32_t*)(smem + OQ_L + r * 144 + 4 * p) = lo;
    }
    for (int i = tid; i < MP * 32; i += 256) {
        int r = i >> 5, p = i & 31;
        float2 v = (r < MFEAT) ? *(const float2*)(proj + r * 64 + 2 * p) : make_float2(0.f, 0.f);
        uint32_t hi, lo; split2(v.x, v.y, hi, lo);
        *(uint32_t*)(smem + OP_H + r * 144 + 4 * p) = hi;
        *(uint32_t*)(smem + OP_L + r * 144 + 4 * p) = lo;
    }
    if (tid < 128) {
        float s = 0.f;
        #pragma unroll
        for (int c = 0; c < DDIM; c++) { float x = qb[tid * 64 + c]; s += x * x; }
        ((float*)(smem + O_DG))[tid] = 0.0625f * s;
        ((float*)(smem + O_MPV))[tid] = NEGINF;
    }
    __syncthreads();

    int wr = w & 3, wc = w >> 2, m0 = 32 * wr;

    float accO[9][4];
    #pragma unroll
    for (int n = 0; n < 9; n++)
        #pragma unroll
        for (int x = 0; x < 4; x++) accO[n][x] = 0.f;

    #pragma unroll 1
    for (int ch = 0; ch < 5; ch++) {
        // GEMM1 (3-term): dd chunk [128 rows x 64 cols], this warp: rows m0..m0+31, cols 32*wc..
        float a1[2][4][4];
        #pragma unroll
        for (int mt = 0; mt < 2; mt++)
            #pragma unroll
            for (int n = 0; n < 4; n++)
                #pragma unroll
                for (int x = 0; x < 4; x++) a1[mt][n][x] = 0.f;
        #pragma unroll
        for (int kt = 0; kt < 4; kt++) {
            uint32_t ah[2][4], al[2][4];
            int arow = lane & 15, koff = (lane >> 4) * 16;
            #pragma unroll
            for (int mt = 0; mt < 2; mt++) {
                uint32_t a = sb + OQ_H + (uint32_t)(m0 + 16 * mt + arow) * 144 + kt * 32 + koff;
                ldsm_x4(ah[mt], a);
                ldsm_x4(al[mt], a + (OQ_L - OQ_H));
            }
            uint32_t bhf[4][2], blf[4][2];
            int brow = lane & 7, bk = ((lane >> 3) & 1) * 16;
            #pragma unroll
            for (int n = 0; n < 4; n++) {
                uint32_t a = sb + OP_H + (uint32_t)(ch * 64 + 32 * wc + 8 * n + brow) * 144 + kt * 32 + bk;
                ldsm_x2(bhf[n], a);
                ldsm_x2(blf[n], a + (OP_L - OP_H));
            }
            #pragma unroll
            for (int mt = 0; mt < 2; mt++)
                #pragma unroll
                for (int n = 0; n < 4; n++) {
                    mma_bf16(a1[mt][n], ah[mt], bhf[n]);
                    mma_bf16(a1[mt][n], ah[mt], blf[n]);
                    mma_bf16(a1[mt][n], al[mt], bhf[n]);
                }
        }
        // per-row chunk max
        #pragma unroll
        for (int mt = 0; mt < 2; mt++) {
            float r0m = NEGINF, r1m = NEGINF;
            #pragma unroll
            for (int n = 0; n < 4; n++) {
                r0m = fmaxf(r0m, fmaxf(a1[mt][n][0], a1[mt][n][1]));
                r1m = fmaxf(r1m, fmaxf(a1[mt][n][2], a1[mt][n][3]));
            }
            r0m = fmaxf(r0m, __shfl_xor_sync(0xffffffffu, r0m, 1));
            r0m = fmaxf(r0m, __shfl_xor_sync(0xffffffffu, r0m, 2));
            r1m = fmaxf(r1m, __shfl_xor_sync(0xffffffffu, r1m, 1));
            r1m = fmaxf(r1m, __shfl_xor_sync(0xffffffffu, r1m, 2));
            if ((lane & 3) == 0) {
                float* rb = (float*)(smem + (wc ? O_RB : O_RA));
                int r0 = m0 + 16 * mt + (lane >> 2);
                rb[r0] = r0m;
                rb[r0 + 8] = r1m;
            }
        }
        __syncthreads();
        if (tid < 128) {
            float Lr = fmaxf(((float*)(smem + O_RA))[tid], ((float*)(smem + O_RB))[tid]);
            float Mp = ((float*)(smem + O_MPV))[tid];
            float Mn = fmaxf(Mp, Lr);
            ((float*)(smem + O_FC))[tid] = __expf(Mp - Mn);
            ((float*)(smem + O_MPV))[tid] = Mn;
            ((float*)(smem + O_OFF))[tid] = ((float*)(smem + O_DG))[tid] + Mn;
        }
        __syncthreads();
        // rescale accO
        {
            float f0 = ((float*)(smem + O_FC))[16 * w + (lane >> 2)];
            float f1 = ((float*)(smem + O_FC))[16 * w + (lane >> 2) + 8];
            #pragma unroll
            for (int n = 0; n < 9; n++) {
                accO[n][0] *= f0; accO[n][1] *= f0;
                accO[n][2] *= f1; accO[n][3] *= f1;
            }
        }
        // epilogue: qp (no eps)
        float* offp = (float*)(smem + O_OFF);
        #pragma unroll
        for (int mt = 0; mt < 2; mt++)
            #pragma unroll
            for (int n = 0; n < 4; n++) {
                int r0 = m0 + 16 * mt + (lane >> 2);
                int col = 32 * wc + 8 * n + 2 * (lane & 3);
                int gm = ch * 64 + col;
                float off0 = offp[r0], off1 = offp[r0 + 8];
                float q0 = (gm     < MFEAT) ? RATIO_C * __expf(a1[mt][n][0] - off0) : 0.f;
                float q1 = (gm + 1 < MFEAT) ? RATIO_C * __expf(a1[mt][n][1] - off0) : 0.f;
                float q2 = (gm     < MFEAT) ? RATIO_C * __expf(a1[mt][n][2] - off1) : 0.f;
                float q3 = (gm + 1 < MFEAT) ? RATIO_C * __expf(a1[mt][n][3] - off1) : 0.f;
                uint32_t hi, lo;
                split2(q0, q1, hi, lo);
                *(uint32_t*)(smem + OS_H + r0 * 144 + col * 2) = hi;
                *(uint32_t*)(smem + OS_L + r0 * 144 + col * 2) = lo;
                split2(q2, q3, hi, lo);
                *(uint32_t*)(smem + OS_H + (r0 + 8) * 144 + col * 2) = hi;
                *(uint32_t*)(smem + OS_L + (r0 + 8) * 144 + col * 2) = lo;
            }
        // stage ctx chunk
        for (int i = tid; i < 72 * 32; i += 256) {
            int e = i >> 5, p = i & 31;
            *(uint32_t*)(smem + OC_H + e * 144 + 4 * p) = g_cthp[((size_t)bh * 72 + e) * 160 + 32 * ch + p];
            *(uint32_t*)(smem + OC_L + e * 144 + 4 * p) = g_ctlp[((size_t)bh * 72 + e) * 160 + 32 * ch + p];
        }
        __syncthreads();

        // GEMM2: accO += qp @ ctx_chunk^T
        int row = 16 * w + (lane & 15), koff2 = (lane >> 4) * 16;
        #pragma unroll
        for (int kt = 0; kt < 4; kt++) {
            uint32_t ah2[4], al2[4];
            uint32_t a = sb + OS_H + (uint32_t)row * 144 + kt * 32 + koff2;
            ldsm_x4(ah2, a);
            ldsm_x4(al2, a + (OS_L - OS_H));
            uint32_t bhf[9][2], blf[9][2];
            int brow = lane & 7, bk = ((lane >> 3) & 1) * 16;
            #pragma unroll
            for (int n = 0; n < 9; n++) {
                uint32_t b = sb + OC_H + (uint32_t)(8 * n + brow) * 144 + kt * 32 + bk;
                ldsm_x2(bhf[n], b);
                ldsm_x2(blf[n], b + (OC_L - OC_H));
            }
            #pragma unroll
            for (int n = 0; n < 9; n++) {
                mma_bf16(accO[n], ah2, bhf[n]);
                mma_bf16(accO[n], ah2, blf[n]);
                mma_bf16(accO[n], al2, bhf[n]);
            }
        }
        __syncthreads();
    }

    // analytic EPS: accO[n][..] += ratio*EPS * ctxsum[col]
    #pragma unroll
    for (int n = 0; n < 9; n++) {
        int col = 8 * n + 2 * (lane & 3);
        float cs0 = g_ctxsum[bh * 72 + col];
        float cs1 = g_ctxsum[bh * 72 + col + 1];
        accO[n][0] += REPS_C * cs0; accO[n][1] += REPS_C * cs1;
        accO[n][2] += REPS_C * cs0; accO[n][3] += REPS_C * cs1;
    }

    float d0 = __shfl_sync(0xffffffffu, accO[8][0], lane & ~3);
    float d1 = __shfl_sync(0xffffffffu, accO[8][2], lane & ~3);
    float i0 = 1.0f / d0, i1 = 1.0f / d1;
    int r0 = nt * 128 + 16 * w + (lane >> 2);
    float* ob = out + (size_t)bh * NSEQ * DDIM;
    #pragma unroll
    for (int n = 0; n < 8; n++) {
        int col = 8 * n + 2 * (lane & 3);
        *(float2*)(ob + (size_t)r0 * DDIM + col) = make_float2(i0 * accO[n][0], i0 * accO[n][1]);
        *(float2*)(ob + (size_t)(r0 + 8) * DDIM + col) = make_float2(i1 * accO[n][2], i1 * accO[n][3]);
    }
}

// ---------------------------------------------------------------------------
extern "C" void kernel_launch(void* const* d_in, const int* in_sizes, int n_in,
                              void* d_out, int out_size) {
    const float* q    = (const float*)d_in[0];
    const float* k    = (const float*)d_in[1];
    const float* v    = (const float*)d_in[2];
    const float* proj = (const float*)d_in[3];
    float* out = (float*)d_out;

    cudaFuncSetAttribute(ctx_fused, cudaFuncAttributeMaxDynamicSharedMemorySize, CX_SZ);
    cudaFuncSetAttribute(out_fused, cudaFuncAttributeMaxDynamicSharedMemorySize, OS2_SZ);

    init_kernel<<<1, 32>>>();
    ctx_fused<<<dim3(2 * KSPL, BH), 320, CX_SZ>>>(k, v, proj);
    convert_kernel<<<dim3(72, BH), 160>>>();
    out_fused<<<dim3(NT, BH), 256, OS2_SZ>>>(q, proj, out);
}

// round 9
// speedup vs baseline: 1.6401x; 1.6401x over previous
#include <cuda_runtime.h>
#include <cuda_bf16.h>
#include <cstdint>

#define BH    32
#define NSEQ  4096
#define DDIM  64
#define MFEAT 266
#define MP    320
#define NT    32
#define KSPL  16
#define KSEG  (NSEQ / KSPL)

#define DNORM   0.35355339059327373f
#define RATIO_C 0.061313933948496576f
#define REPS_C  6.1313933948496576e-06f   // ratio * 1e-4
#define NEGINF  -1.0e30f

// ---------------- global scratch (static; no cudaMalloc) --------------------
__device__ float        g_ctxS[(size_t)KSPL * BH * 72 * MP];   // K-split ctx^T partials
__device__ float        g_ctxM[KSPL * BH * 2];                 // per-slab stabilizer max
__device__ float        g_ctxsum[BH * 72];                     // sum_m ctx[m,e]
__device__ uint32_t     g_cthp[(size_t)BH * 72 * 160];         // ctx^T hi bf16 pairs
__device__ uint32_t     g_ctlp[(size_t)BH * 72 * 160];         // ctx^T lo bf16 pairs
__device__ unsigned int g_kmax_enc;

__device__ __forceinline__ unsigned int enc_f(float f) {
    unsigned int u = __float_as_uint(f);
    return (u & 0x80000000u) ? ~u : (u | 0x80000000u);
}
__device__ __forceinline__ float dec_f(unsigned int k) {
    return (k & 0x80000000u) ? __uint_as_float(k & 0x7fffffffu) : __uint_as_float(~k);
}
__device__ __forceinline__ uint32_t smem_u32(const void* p) {
    uint32_t a;
    asm("{ .reg .u64 t; cvta.to.shared.u64 t, %1; cvt.u32.u64 %0, t; }" : "=r"(a) : "l"(p));
    return a;
}
__device__ __forceinline__ uint32_t packbf(float a, float b) {
    __nv_bfloat162 t = __floats2bfloat162_rn(a, b);
    return reinterpret_cast<uint32_t&>(t);
}
__device__ __forceinline__ void split2(float a, float b, uint32_t& hi, uint32_t& lo) {
    __nv_bfloat16 ha = __float2bfloat16_rn(a), hb = __float2bfloat16_rn(b);
    float ra = a - __bfloat162float(ha), rb = b - __bfloat162float(hb);
    __nv_bfloat162 H; H.x = ha; H.y = hb;
    hi = reinterpret_cast<uint32_t&>(H);
    lo = packbf(ra, rb);
}

// ---------------- mma.sync + ldmatrix helpers -------------------------------
__device__ __forceinline__ void ldsm_x4(uint32_t* r, uint32_t addr) {
    asm volatile("ldmatrix.sync.aligned.m8n8.x4.shared.b16 {%0,%1,%2,%3}, [%4];"
        : "=r"(r[0]), "=r"(r[1]), "=r"(r[2]), "=r"(r[3]) : "r"(addr));
}
__device__ __forceinline__ void ldsm_x2(uint32_t* r, uint32_t addr) {
    asm volatile("ldmatrix.sync.aligned.m8n8.x2.shared.b16 {%0,%1}, [%2];"
        : "=r"(r[0]), "=r"(r[1]) : "r"(addr));
}
__device__ __forceinline__ void ldsm_x2t(uint32_t* r, uint32_t addr) {
    asm volatile("ldmatrix.sync.aligned.m8n8.x2.trans.shared.b16 {%0,%1}, [%2];"
        : "=r"(r[0]), "=r"(r[1]) : "r"(addr));
}
__device__ __forceinline__ void mma_bf16(float* c, const uint32_t* a, const uint32_t* b) {
    asm volatile("mma.sync.aligned.m16n8k16.row.col.f32.bf16.bf16.f32 "
        "{%0,%1,%2,%3}, {%4,%5,%6,%7}, {%8,%9}, {%0,%1,%2,%3};"
        : "+f"(c[0]), "+f"(c[1]), "+f"(c[2]), "+f"(c[3])
        : "r"(a[0]), "r"(a[1]), "r"(a[2]), "r"(a[3]), "r"(b[0]), "r"(b[1]));
}

// ---------------------------------------------------------------------------
__global__ void init_kernel() {
    if (threadIdx.x == 0 && blockIdx.x == 0) g_kmax_enc = 0u;
}

// ---------------------------------------------------------------------------
// ctx_fused: ddT[160 m x 64 n] = proj @ (DN k)^T per chunk (A=proj persistent
// frags). Online block max -> rescale -> exp in REGISTERS (C->A remap) ->
// GEMM2 kpT @ [v|1]. Ones-ROW at m=266 -> vsum (rescale-exempt).
// grid (2*KSPL, BH), block 320 (10 warps x 16 m-rows).
// ---------------------------------------------------------------------------
#define CP_H 0
#define CP_L 23040
#define CK_H 46080
#define CK_L 55296
#define CW_H 64512
#define CW_L 75776
#define CD_  87040
#define C_MX 87296
#define CX_SZ 87360

__global__ void __launch_bounds__(320, 1) ctx_fused(const float* __restrict__ k_in,
                                                    const float* __restrict__ v_in,
                                                    const float* __restrict__ proj) {
    extern __shared__ char smem[];
    uint32_t sb = smem_u32(smem);
    int tid = threadIdx.x, w = tid >> 5, lane = tid & 31;
    int bh = blockIdx.y, mhalf = blockIdx.x & 1, ks = blockIdx.x >> 1;

    // stage proj half [160 m rows x 64 d] hi/lo (persistent)
    for (int i = tid; i < 160 * 32; i += 320) {
        int r = i >> 5, p = i & 31;
        int m = mhalf * 160 + r;
        float2 v = (m < MFEAT) ? *(const float2*)(proj + m * 64 + 2 * p) : make_float2(0.f, 0.f);
        uint32_t hi, lo; split2(v.x, v.y, hi, lo);
        *(uint32_t*)(smem + CP_H + r * 144 + 4 * p) = hi;
        *(uint32_t*)(smem + CP_L + r * 144 + 4 * p) = lo;
    }
    __syncthreads();

    int arow = lane & 15, koff = (lane >> 4) * 16;
    int brow = lane & 7,  bk = ((lane >> 3) & 1) * 16;
    int krb  = (lane & 7) + 8 * ((lane >> 3) & 1);
    int qrow = lane >> 2, qcol2 = 2 * (lane & 3);
    int mr0 = mhalf * 160 + 16 * w + qrow;      // global m row0; row1 = mr0+8

    // persistent A = proj fragments
    uint32_t aph[4][4], apl[4][4];
    #pragma unroll
    for (int kt = 0; kt < 4; kt++) {
        uint32_t a = sb + CP_H + (uint32_t)(16 * w + arow) * 144 + kt * 32 + koff;
        ldsm_x4(aph[kt], a);
        ldsm_x4(apl[kt], a + (CP_L - CP_H));
    }

    float accC[9][4];
    #pragma unroll
    for (int n = 0; n < 9; n++)
        #pragma unroll
        for (int x = 0; x < 4; x++) accC[n][x] = 0.f;
    float Mold = NEGINF;

    #pragma unroll 1
    for (int c = 0; c < KSEG / 64; c++) {
        int n0 = ks * KSEG + c * 64;
        __syncthreads();
        const float* kb = k_in + ((size_t)bh * NSEQ + n0) * DDIM;
        for (int i = tid; i < 64 * 32; i += 320) {
            int r = i >> 5, p = i & 31;
            float2 v = *(const float2*)(kb + r * 64 + 2 * p);
            uint32_t hi, lo; split2(DNORM * v.x, DNORM * v.y, hi, lo);
            *(uint32_t*)(smem + CK_H + r * 144 + 4 * p) = hi;
            *(uint32_t*)(smem + CK_L + r * 144 + 4 * p) = lo;
        }
        const float* vb = v_in + ((size_t)bh * NSEQ + n0) * DDIM;
        for (int i = tid; i < 64 * 36; i += 320) {
            int r = i / 36, p = i % 36;
            int e = 2 * p;
            float2 wv;
            if (e < 64)       wv = *(const float2*)(vb + r * 64 + e);
            else if (e == 64) wv = make_float2(1.f, 0.f);
            else              wv = make_float2(0.f, 0.f);
            uint32_t hi, lo; split2(wv.x, wv.y, hi, lo);
            *(uint32_t*)(smem + CW_H + r * 176 + 4 * p) = hi;
            *(uint32_t*)(smem + CW_L + r * 176 + 4 * p) = lo;
        }
        if (tid < 64) {
            float s = 0.f;
            #pragma unroll
            for (int d = 0; d < DDIM; d++) { float x = kb[tid * 64 + d]; s += x * x; }
            ((float*)(smem + CD_))[tid] = 0.0625f * s;
        }
        __syncthreads();

        // GEMM1': ddT[m=16w rows][n=64 cols], 3-term
        float c1[8][4];
        #pragma unroll
        for (int n = 0; n < 8; n++)
            #pragma unroll
            for (int x = 0; x < 4; x++) c1[n][x] = 0.f;
        #pragma unroll
        for (int kt = 0; kt < 4; kt++) {
            uint32_t bkh[8][2], bkl[8][2];
            #pragma unroll
            for (int n = 0; n < 8; n++) {
                uint32_t a = sb + CK_H + (uint32_t)(8 * n + brow) * 144 + kt * 32 + bk;
                ldsm_x2(bkh[n], a);
                ldsm_x2(bkl[n], a + (CK_L - CK_H));
            }
            #pragma unroll
            for (int n = 0; n < 8; n++) {
                mma_bf16(c1[n], aph[kt], bkh[n]);
                mma_bf16(c1[n], aph[kt], bkl[n]);
                mma_bf16(c1[n], apl[kt], bkh[n]);
            }
        }

        // block max over valid m rows
        bool v0 = mr0 < MFEAT, v1 = (mr0 + 8) < MFEAT;
        float lm = NEGINF;
        #pragma unroll
        for (int n = 0; n < 8; n++) {
            if (v0) lm = fmaxf(lm, fmaxf(c1[n][0], c1[n][1]));
            if (v1) lm = fmaxf(lm, fmaxf(c1[n][2], c1[n][3]));
        }
        #pragma unroll
        for (int off = 16; off; off >>= 1) lm = fmaxf(lm, __shfl_xor_sync(0xffffffffu, lm, off));
        if (lane == 0) ((float*)(smem + C_MX))[w] = lm;
        __syncthreads();
        float bmax = NEGINF;
        #pragma unroll
        for (int i = 0; i < 10; i++) bmax = fmaxf(bmax, ((float*)(smem + C_MX))[i]);
        float Mnew = fmaxf(Mold, bmax);
        float factor = __expf(Mold - Mnew);

        // rescale accC (ones-row m==266 exempt)
        {
            float f0 = (mr0 == MFEAT) ? 1.f : factor;
            float f1 = (mr0 + 8 == MFEAT) ? 1.f : factor;
            #pragma unroll
            for (int n = 0; n < 9; n++) {
                accC[n][0] *= f0; accC[n][1] *= f0;
                accC[n][2] *= f1; accC[n][3] *= f1;
            }
        }

        // GEMM2: accC[m, e] += kpT @ w; A from registers (exp + C->A remap)
        float* dg = (float*)(smem + CD_);
        #pragma unroll
        for (int kt2 = 0; kt2 < 4; kt2++) {
            int u = 2 * kt2, vt = u + 1;
            int ncol = 16 * kt2 + qcol2;
            float dgu0 = dg[ncol],     dgu1 = dg[ncol + 1];
            float dgv0 = dg[ncol + 8], dgv1 = dg[ncol + 9];
            uint32_t qa_h[4], qa_l[4];
            // row0, tiles u and v
            {
                float a0, a1, a2, a3;
                if (mr0 < MFEAT) {
                    a0 = RATIO_C * __expf(c1[u][0] - dgu0 - Mnew);
                    a1 = RATIO_C * __expf(c1[u][1] - dgu1 - Mnew);
                    a2 = RATIO_C * __expf(c1[vt][0] - dgv0 - Mnew);
                    a3 = RATIO_C * __expf(c1[vt][1] - dgv1 - Mnew);
                } else if (mr0 == MFEAT) { a0 = a1 = a2 = a3 = 1.f; }
                else { a0 = a1 = a2 = a3 = 0.f; }
                split2(a0, a1, qa_h[0], qa_l[0]);
                split2(a2, a3, qa_h[2], qa_l[2]);
            }
            // row1
            {
                int m1 = mr0 + 8;
                float a0, a1, a2, a3;
                if (m1 < MFEAT) {
                    a0 = RATIO_C * __expf(c1[u][2] - dgu0 - Mnew);
                    a1 = RATIO_C * __expf(c1[u][3] - dgu1 - Mnew);
                    a2 = RATIO_C * __expf(c1[vt][2] - dgv0 - Mnew);
                    a3 = RATIO_C * __expf(c1[vt][3] - dgv1 - Mnew);
                } else if (m1 == MFEAT) { a0 = a1 = a2 = a3 = 1.f; }
                else { a0 = a1 = a2 = a3 = 0.f; }
                split2(a0, a1, qa_h[1], qa_l[1]);
                split2(a2, a3, qa_h[3], qa_l[3]);
            }
            uint32_t bwh[9][2], bwl[9][2];
            #pragma unroll
            for (int nE = 0; nE < 9; nE++) {
                uint32_t b = sb + CW_H + (uint32_t)(kt2 * 16 + krb) * 176 + 16 * nE;
                ldsm_x2t(bwh[nE], b);
                ldsm_x2t(bwl[nE], b + (CW_L - CW_H));
            }
            #pragma unroll
            for (int nE = 0; nE < 9; nE++) {
                mma_bf16(accC[nE], qa_h, bwh[nE]);
                mma_bf16(accC[nE], qa_h, bwl[nE]);
                mma_bf16(accC[nE], qa_l, bwh[nE]);
            }
        }
        Mold = Mnew;
    }

    float* slab = g_ctxS + ((size_t)(ks * BH + bh)) * 72 * MP;
    #pragma unroll
    for (int nE = 0; nE < 9; nE++) {
        int e = 8 * nE + qcol2;
        slab[(size_t)e * MP + mr0]           = accC[nE][0];
        slab[(size_t)(e + 1) * MP + mr0]     = accC[nE][1];
        slab[(size_t)e * MP + mr0 + 8]       = accC[nE][2];
        slab[(size_t)(e + 1) * MP + mr0 + 8] = accC[nE][3];
    }
    if (tid == 0) {
        g_ctxM[(ks * BH + bh) * 2 + mhalf] = Mold;
        atomicMax(&g_kmax_enc, enc_f(Mold));
    }
}

// ---------------------------------------------------------------------------
// convert: merge slabs with e^{M_s - G}; add analytic EPS; bf16 split; ctxsum.
// ---------------------------------------------------------------------------
__global__ void __launch_bounds__(160) convert_kernel() {
    __shared__ float sc[KSPL * 2];
    __shared__ float vs_sh;
    __shared__ float red[5];
    int e = blockIdx.x, bh = blockIdx.y, t = threadIdx.x;
    float G = dec_f(g_kmax_enc);
    if (t < KSPL * 2) sc[t] = __expf(g_ctxM[((t >> 1) * BH + bh) * 2 + (t & 1)] - G);
    if (t == 0) {
        float v = 0.f;
        #pragma unroll
        for (int ks = 0; ks < KSPL; ks++)
            v += g_ctxS[(((size_t)(ks * BH + bh)) * 72 + e) * MP + MFEAT];
        vs_sh = v;
    }
    __syncthreads();

    int mh = (t >= 80) ? 1 : 0;
    float sx = 0.f, sy = 0.f;
    #pragma unroll
    for (int ks = 0; ks < KSPL; ks++) {
        float2 vv = *(const float2*)(g_ctxS + (((size_t)(ks * BH + bh)) * 72 + e) * MP + 2 * t);
        float s = sc[ks * 2 + mh];
        sx += s * vv.x; sy += s * vv.y;
    }
    float eps_add = REPS_C * vs_sh;
    int m0 = 2 * t;
    float fx = (m0     < MFEAT) ? sx + eps_add : 0.f;
    float fy = (m0 + 1 < MFEAT) ? sy + eps_add : 0.f;
    uint32_t hi, lo; split2(fx, fy, hi, lo);
    g_cthp[((size_t)bh * 72 + e) * 160 + t] = hi;
    g_ctlp[((size_t)bh * 72 + e) * 160 + t] = lo;

    float part = fx + fy;
    #pragma unroll
    for (int off = 16; off; off >>= 1) part += __shfl_xor_sync(0xffffffffu, part, off);
    if ((t & 31) == 0) red[t >> 5] = part;
    __syncthreads();
    if (t == 0) g_ctxsum[bh * 72 + e] = red[0] + red[1] + red[2] + red[3] + red[4];
}

// ---------------------------------------------------------------------------
// out_fused: warp owns 16 q-rows x full 64-col chunk. Per-chunk: dd GEMM ->
// quad-shfl row max (register-online) -> rescale -> exp C->A remap in regs ->
// GEMM2 vs ctx chunk. smem 76.5KB -> 2 CTAs/SM. grid (NT, BH), block 256.
// ---------------------------------------------------------------------------
#define OQ_H 0
#define OQ_L 18432
#define OP_H 36864
#define OP_L 46080
#define OC_H 55296
#define OC_L 65664
#define O_DG 76032
#define O_SZ 76544

__global__ void __launch_bounds__(256, 2) out_fused(const float* __restrict__ q_in,
                                                    const float* __restrict__ proj,
                                                    float* __restrict__ out) {
    extern __shared__ char smem[];
    uint32_t sb = smem_u32(smem);
    int tid = threadIdx.x, w = tid >> 5, lane = tid & 31;
    int bh = blockIdx.y, nt = blockIdx.x;
    const float* qb = q_in + ((size_t)bh * NSEQ + nt * 128) * DDIM;

    for (int i = tid; i < 128 * 32; i += 256) {
        int r = i >> 5, p = i & 31;
        float2 v = *(const float2*)(qb + r * 64 + 2 * p);
        uint32_t hi, lo; split2(DNORM * v.x, DNORM * v.y, hi, lo);
        *(uint32_t*)(smem + OQ_H + r * 144 + 4 * p) = hi;
        *(uint32_t*)(smem + OQ_L + r * 144 + 4 * p) = lo;
    }
    if (tid < 128) {
        float s = 0.f;
        #pragma unroll
        for (int d = 0; d < DDIM; d++) { float x = qb[tid * 64 + d]; s += x * x; }
        ((float*)(smem + O_DG))[tid] = 0.0625f * s;
    }
    __syncthreads();

    int arow = lane & 15, koff = (lane >> 4) * 16;
    int brow = lane & 7,  bk = ((lane >> 3) & 1) * 16;
    int qrow = lane >> 2, qcol2 = 2 * (lane & 3);
    int m0 = 16 * w;
    float dg0 = ((float*)(smem + O_DG))[m0 + qrow];
    float dg1 = ((float*)(smem + O_DG))[m0 + qrow + 8];
    float M0 = NEGINF, M1 = NEGINF;

    float accO[9][4];
    #pragma unroll
    for (int n = 0; n < 9; n++)
        #pragma unroll
        for (int x = 0; x < 4; x++) accO[n][x] = 0.f;

    #pragma unroll 1
    for (int ch = 0; ch < 5; ch++) {
        __syncthreads();
        // stage proj chunk [64 m rows x 64 d] hi/lo
        for (int i = tid; i < 64 * 32; i += 256) {
            int r = i >> 5, p = i & 31;
            int m = ch * 64 + r;
            float2 v = (m < MFEAT) ? *(const float2*)(proj + m * 64 + 2 * p) : make_float2(0.f, 0.f);
            uint32_t hi, lo; split2(v.x, v.y, hi, lo);
            *(uint32_t*)(smem + OP_H + r * 144 + 4 * p) = hi;
            *(uint32_t*)(smem + OP_L + r * 144 + 4 * p) = lo;
        }
        // stage ctx chunk
        for (int i = tid; i < 72 * 32; i += 256) {
            int e = i >> 5, p = i & 31;
            *(uint32_t*)(smem + OC_H + e * 144 + 4 * p) = g_cthp[((size_t)bh * 72 + e) * 160 + 32 * ch + p];
            *(uint32_t*)(smem + OC_L + e * 144 + 4 * p) = g_ctlp[((size_t)bh * 72 + e) * 160 + 32 * ch + p];
        }
        __syncthreads();

        // GEMM1: dd[16 rows x 64 m-cols] (3-term)
        float a1[8][4];
        #pragma unroll
        for (int n = 0; n < 8; n++)
            #pragma unroll
            for (int x = 0; x < 4; x++) a1[n][x] = 0.f;
        #pragma unroll
        for (int kt = 0; kt < 4; kt++) {
            uint32_t ah[4], al[4];
            uint32_t a = sb + OQ_H + (uint32_t)(m0 + arow) * 144 + kt * 32 + koff;
            ldsm_x4(ah, a);
            ldsm_x4(al, a + (OQ_L - OQ_H));
            uint32_t bh8[8][2], bl8[8][2];
            #pragma unroll
            for (int n = 0; n < 8; n++) {
                uint32_t b = sb + OP_H + (uint32_t)(8 * n + brow) * 144 + kt * 32 + bk;
                ldsm_x2(bh8[n], b);
                ldsm_x2(bl8[n], b + (OP_L - OP_H));
            }
            #pragma unroll
            for (int n = 0; n < 8; n++) {
                mma_bf16(a1[n], ah, bh8[n]);
                mma_bf16(a1[n], ah, bl8[n]);
                mma_bf16(a1[n], al, bh8[n]);
            }
        }

        // per-row online max (quad shfl only)
        float lm0 = NEGINF, lm1 = NEGINF;
        #pragma unroll
        for (int n = 0; n < 8; n++) {
            int gm = ch * 64 + 8 * n + qcol2;
            if (gm < MFEAT)     { lm0 = fmaxf(lm0, a1[n][0]); lm1 = fmaxf(lm1, a1[n][2]); }
            if (gm + 1 < MFEAT) { lm0 = fmaxf(lm0, a1[n][1]); lm1 = fmaxf(lm1, a1[n][3]); }
        }
        lm0 = fmaxf(lm0, __shfl_xor_sync(0xffffffffu, lm0, 1));
        lm0 = fmaxf(lm0, __shfl_xor_sync(0xffffffffu, lm0, 2));
        lm1 = fmaxf(lm1, __shfl_xor_sync(0xffffffffu, lm1, 1));
        lm1 = fmaxf(lm1, __shfl_xor_sync(0xffffffffu, lm1, 2));
        float Mn0 = fmaxf(M0, lm0), Mn1 = fmaxf(M1, lm1);
        float f0 = __expf(M0 - Mn0), f1 = __expf(M1 - Mn1);
        M0 = Mn0; M1 = Mn1;
        float off0 = dg0 + Mn0, off1 = dg1 + Mn1;
        #pragma unroll
        for (int n = 0; n < 9; n++) {
            accO[n][0] *= f0; accO[n][1] *= f0;
            accO[n][2] *= f1; accO[n][3] *= f1;
        }

        // GEMM2: accO += qp @ ctx^T; A from registers (exp + C->A remap)
        #pragma unroll
        for (int kt2 = 0; kt2 < 4; kt2++) {
            int u = 2 * kt2, vt = u + 1;
            int gmu = ch * 64 + 8 * u + qcol2;
            int gmv = gmu + 8;
            uint32_t qa_h[4], qa_l[4];
            {
                float a0 = (gmu     < MFEAT) ? RATIO_C * __expf(a1[u][0] - off0) : 0.f;
                float a1v = (gmu + 1 < MFEAT) ? RATIO_C * __expf(a1[u][1] - off0) : 0.f;
                float a2 = (gmv     < MFEAT) ? RATIO_C * __expf(a1[vt][0] - off0) : 0.f;
                float a3 = (gmv + 1 < MFEAT) ? RATIO_C * __expf(a1[vt][1] - off0) : 0.f;
                split2(a0, a1v, qa_h[0], qa_l[0]);
                split2(a2, a3, qa_h[2], qa_l[2]);
            }
            {
                float a0 = (gmu     < MFEAT) ? RATIO_C * __expf(a1[u][2] - off1) : 0.f;
                float a1v = (gmu + 1 < MFEAT) ? RATIO_C * __expf(a1[u][3] - off1) : 0.f;
                float a2 = (gmv     < MFEAT) ? RATIO_C * __expf(a1[vt][2] - off1) : 0.f;
                float a3 = (gmv + 1 < MFEAT) ? RATIO_C * __expf(a1[vt][3] - off1) : 0.f;
                split2(a0, a1v, qa_h[1], qa_l[1]);
                split2(a2, a3, qa_h[3], qa_l[3]);
            }
            uint32_t cbh[9][2], cbl[9][2];
            #pragma unroll
            for (int n = 0; n < 9; n++) {
                uint32_t b = sb + OC_H + (uint32_t)(8 * n + brow) * 144 + kt2 * 32 + bk;
                ldsm_x2(cbh[n], b);
                ldsm_x2(cbl[n], b + (OC_L - OC_H));
            }
            #pragma unroll
            for (int n = 0; n < 9; n++) {
                mma_bf16(accO[n], qa_h, cbh[n]);
                mma_bf16(accO[n], qa_h, cbl[n]);
                mma_bf16(accO[n], qa_l, cbh[n]);
            }
        }
    }

    // analytic EPS + denominator + store
    #pragma unroll
    for (int n = 0; n < 9; n++) {
        int col = 8 * n + qcol2;
        float cs0 = g_ctxsum[bh * 72 + col];
        float cs1 = g_ctxsum[bh * 72 + col + 1];
        accO[n][0] += REPS_C * cs0; accO[n][1] += REPS_C * cs1;
        accO[n][2] += REPS_C * cs0; accO[n][3] += REPS_C * cs1;
    }
    float d0 = __shfl_sync(0xffffffffu, accO[8][0], lane & ~3);
    float d1 = __shfl_sync(0xffffffffu, accO[8][2], lane & ~3);
    float i0 = 1.0f / d0, i1 = 1.0f / d1;
    int r0g = nt * 128 + m0 + qrow;
    float* ob = out + (size_t)bh * NSEQ * DDIM;
    #pragma unroll
    for (int n = 0; n < 8; n++) {
        int col = 8 * n + qcol2;
        *(float2*)(ob + (size_t)r0g * DDIM + col) = make_float2(i0 * accO[n][0], i0 * accO[n][1]);
        *(float2*)(ob + (size_t)(r0g + 8) * DDIM + col) = make_float2(i1 * accO[n][2], i1 * accO[n][3]);
    }
}

// ---------------------------------------------------------------------------
extern "C" void kernel_launch(void* const* d_in, const int* in_sizes, int n_in,
                              void* d_out, int out_size) {
    const float* q    = (const float*)d_in[0];
    const float* k    = (const float*)d_in[1];
    const float* v    = (const float*)d_in[2];
    const float* proj = (const float*)d_in[3];
    float* out = (float*)d_out;

    cudaFuncSetAttribute(ctx_fused, cudaFuncAttributeMaxDynamicSharedMemorySize, CX_SZ);
    cudaFuncSetAttribute(out_fused, cudaFuncAttributeMaxDynamicSharedMemorySize, O_SZ);

    init_kernel<<<1, 32>>>();
    ctx_fused<<<dim3(2 * KSPL, BH), 320, CX_SZ>>>(k, v, proj);
    convert_kernel<<<dim3(72, BH), 160>>>();
    out_fused<<<dim3(NT, BH), 256, O_SZ>>>(q, proj, out);
}

// round 10
// speedup vs baseline: 2.4211x; 1.4762x over previous
#include <cuda_runtime.h>
#include <cuda_bf16.h>
#include <cstdint>

#define BH    32
#define NSEQ  4096
#define DDIM  64
#define MFEAT 266
#define MP    320
#define NT    32
#define KSPL  16
#define KSEG  (NSEQ / KSPL)

#define DNORM   0.35355339059327373f
#define RATIO_C 0.061313933948496576f
#define REPS_C  6.1313933948496576e-06f   // ratio * 1e-4
#define NEGINF  -1.0e30f

// ---------------- global scratch (static; no cudaMalloc) --------------------
__device__ float        g_ctxS[(size_t)KSPL * BH * 72 * MP];   // K-split ctx^T partials
__device__ float        g_ctxM[KSPL * BH * 3];                 // per (slab, mtile) stabilizer
__device__ float        g_ctxsum[BH * 72];                     // sum_m ctx[m,e]
__device__ uint32_t     g_cthp[(size_t)BH * 72 * 160];         // ctx^T hi bf16 pairs
__device__ uint32_t     g_ctlp[(size_t)BH * 72 * 160];         // ctx^T lo bf16 pairs
__device__ unsigned int g_kmax_enc;

__device__ __forceinline__ unsigned int enc_f(float f) {
    unsigned int u = __float_as_uint(f);
    return (u & 0x80000000u) ? ~u : (u | 0x80000000u);
}
__device__ __forceinline__ float dec_f(unsigned int k) {
    return (k & 0x80000000u) ? __uint_as_float(k & 0x7fffffffu) : __uint_as_float(~k);
}
__device__ __forceinline__ uint32_t smem_u32(const void* p) {
    uint32_t a;
    asm("{ .reg .u64 t; cvta.to.shared.u64 t, %1; cvt.u32.u64 %0, t; }" : "=r"(a) : "l"(p));
    return a;
}
__device__ __forceinline__ uint32_t packbf(float a, float b) {
    __nv_bfloat162 t = __floats2bfloat162_rn(a, b);
    return reinterpret_cast<uint32_t&>(t);
}
__device__ __forceinline__ void split2(float a, float b, uint32_t& hi, uint32_t& lo) {
    __nv_bfloat16 ha = __float2bfloat16_rn(a), hb = __float2bfloat16_rn(b);
    float ra = a - __bfloat162float(ha), rb = b - __bfloat162float(hb);
    __nv_bfloat162 H; H.x = ha; H.y = hb;
    hi = reinterpret_cast<uint32_t&>(H);
    lo = packbf(ra, rb);
}

// ---------------- mma.sync + ldmatrix helpers -------------------------------
__device__ __forceinline__ void ldsm_x4(uint32_t* r, uint32_t addr) {
    asm volatile("ldmatrix.sync.aligned.m8n8.x4.shared.b16 {%0,%1,%2,%3}, [%4];"
        : "=r"(r[0]), "=r"(r[1]), "=r"(r[2]), "=r"(r[3]) : "r"(addr));
}
__device__ __forceinline__ void ldsm_x2(uint32_t* r, uint32_t addr) {
    asm volatile("ldmatrix.sync.aligned.m8n8.x2.shared.b16 {%0,%1}, [%2];"
        : "=r"(r[0]), "=r"(r[1]) : "r"(addr));
}
__device__ __forceinline__ void ldsm_x2t(uint32_t* r, uint32_t addr) {
    asm volatile("ldmatrix.sync.aligned.m8n8.x2.trans.shared.b16 {%0,%1}, [%2];"
        : "=r"(r[0]), "=r"(r[1]) : "r"(addr));
}
__device__ __forceinline__ void mma_bf16(float* c, const uint32_t* a, const uint32_t* b) {
    asm volatile("mma.sync.aligned.m16n8k16.row.col.f32.bf16.bf16.f32 "
        "{%0,%1,%2,%3}, {%4,%5,%6,%7}, {%8,%9}, {%0,%1,%2,%3};"
        : "+f"(c[0]), "+f"(c[1]), "+f"(c[2]), "+f"(c[3])
        : "r"(a[0]), "r"(a[1]), "r"(a[2]), "r"(a[3]), "r"(b[0]), "r"(b[1]));
}

// ---------------------------------------------------------------------------
__global__ void init_kernel() {
    if (threadIdx.x == 0 && blockIdx.x == 0) g_kmax_enc = 0u;
}

// ---------------------------------------------------------------------------
// ctx_fused: per CTA = (mtile of 128 m-rows, K-split seg). Per 64-row n-chunk:
// ddT[16w rows x 64 n] = proj @ (DN k)^T (3-term) -> block max -> rescale ->
// exp in registers (C->A remap) -> GEMM2 kpT @ [v|1]. Warp-tiles with m>=272
// skip MMA entirely. Ones-ROW at m=266 -> vsum (rescale-exempt).
// grid (3*KSPL, BH), block 256 (8 warps), 2 CTAs/SM.
// ---------------------------------------------------------------------------
#define CP_H 0
#define CP_L 18432
#define CK_H 36864
#define CK_L 46080
#define CW_H 55296
#define CW_L 66560
#define CD_  77824
#define C_MX 78080
#define CX_SZ 78336

__global__ void __launch_bounds__(256, 2) ctx_fused(const float* __restrict__ k_in,
                                                    const float* __restrict__ v_in,
                                                    const float* __restrict__ proj) {
    extern __shared__ char smem[];
    uint32_t sb = smem_u32(smem);
    int tid = threadIdx.x, w = tid >> 5, lane = tid & 31;
    int bh = blockIdx.y, mtile = blockIdx.x % 3, ks = blockIdx.x / 3;

    int arow = lane & 15, koff = (lane >> 4) * 16;
    int brow = lane & 7,  bk = ((lane >> 3) & 1) * 16;
    int krb  = (lane & 7) + 8 * ((lane >> 3) & 1);
    int qrow = lane >> 2, qcol2 = 2 * (lane & 3);
    int tileid = 8 * mtile + w;
    bool wvalid = tileid <= 16;                  // tiles covering m < 272
    int mr0 = mtile * 128 + 16 * w + qrow;       // global m row0; row1 = mr0+8

    // stage proj tile [128 m rows x 64 d] hi/lo (persistent)
    for (int i = tid; i < 128 * 32; i += 256) {
        int r = i >> 5, p = i & 31;
        int m = mtile * 128 + r;
        float2 v = (m < MFEAT) ? *(const float2*)(proj + m * 64 + 2 * p) : make_float2(0.f, 0.f);
        uint32_t hi, lo; split2(v.x, v.y, hi, lo);
        *(uint32_t*)(smem + CP_H + r * 144 + 4 * p) = hi;
        *(uint32_t*)(smem + CP_L + r * 144 + 4 * p) = lo;
    }

    float accC[9][4];
    #pragma unroll
    for (int n = 0; n < 9; n++)
        #pragma unroll
        for (int x = 0; x < 4; x++) accC[n][x] = 0.f;
    float Mold = NEGINF;

    #pragma unroll 1
    for (int c = 0; c < KSEG / 64; c++) {
        int n0 = ks * KSEG + c * 64;
        __syncthreads();
        const float* kb = k_in + ((size_t)bh * NSEQ + n0) * DDIM;
        for (int i = tid; i < 64 * 32; i += 256) {
            int r = i >> 5, p = i & 31;
            float2 v = *(const float2*)(kb + r * 64 + 2 * p);
            uint32_t hi, lo; split2(DNORM * v.x, DNORM * v.y, hi, lo);
            *(uint32_t*)(smem + CK_H + r * 144 + 4 * p) = hi;
            *(uint32_t*)(smem + CK_L + r * 144 + 4 * p) = lo;
        }
        const float* vb = v_in + ((size_t)bh * NSEQ + n0) * DDIM;
        for (int i = tid; i < 64 * 36; i += 256) {
            int r = i / 36, p = i % 36;
            int e = 2 * p;
            float2 wv;
            if (e < 64)       wv = *(const float2*)(vb + r * 64 + e);
            else if (e == 64) wv = make_float2(1.f, 0.f);
            else              wv = make_float2(0.f, 0.f);
            uint32_t hi, lo; split2(wv.x, wv.y, hi, lo);
            *(uint32_t*)(smem + CW_H + r * 176 + 4 * p) = hi;
            *(uint32_t*)(smem + CW_L + r * 176 + 4 * p) = lo;
        }
        __syncthreads();

        // diag from staged hi+lo (values already scaled by DN): 0.5*sum x^2
        if (tid < 64) {
            float s = 0.f;
            #pragma unroll
            for (int p = 0; p < 32; p++) {
                uint32_t hu = *(uint32_t*)(smem + CK_H + tid * 144 + 4 * p);
                uint32_t lu = *(uint32_t*)(smem + CK_L + tid * 144 + 4 * p);
                __nv_bfloat162 hb2 = reinterpret_cast<__nv_bfloat162&>(hu);
                __nv_bfloat162 lb2 = reinterpret_cast<__nv_bfloat162&>(lu);
                float x0 = __bfloat162float(hb2.x) + __bfloat162float(lb2.x);
                float x1 = __bfloat162float(hb2.y) + __bfloat162float(lb2.y);
                s += x0 * x0 + x1 * x1;
            }
            ((float*)(smem + CD_))[tid] = 0.5f * s;
        }
        __syncthreads();

        // GEMM1': ddT[16 rows x 64 n], 3-term
        float c1[8][4];
        #pragma unroll
        for (int n = 0; n < 8; n++)
            #pragma unroll
            for (int x = 0; x < 4; x++) c1[n][x] = 0.f;
        if (wvalid) {
            #pragma unroll
            for (int kt = 0; kt < 4; kt++) {
                uint32_t aph[4], apl[4];
                uint32_t a = sb + CP_H + (uint32_t)(16 * w + arow) * 144 + kt * 32 + koff;
                ldsm_x4(aph, a);
                ldsm_x4(apl, a + (CP_L - CP_H));
                uint32_t bkh[8][2], bkl[8][2];
                #pragma unroll
                for (int n = 0; n < 8; n++) {
                    uint32_t b = sb + CK_H + (uint32_t)(8 * n + brow) * 144 + kt * 32 + bk;
                    ldsm_x2(bkh[n], b);
                    ldsm_x2(bkl[n], b + (CK_L - CK_H));
                }
                #pragma unroll
                for (int n = 0; n < 8; n++) {
                    mma_bf16(c1[n], aph, bkh[n]);
                    mma_bf16(c1[n], aph, bkl[n]);
                    mma_bf16(c1[n], apl, bkh[n]);
                }
            }
        }

        // block max over valid m rows
        bool v0 = wvalid && (mr0 < MFEAT), v1 = wvalid && (mr0 + 8 < MFEAT);
        float lm = NEGINF;
        #pragma unroll
        for (int n = 0; n < 8; n++) {
            if (v0) lm = fmaxf(lm, fmaxf(c1[n][0], c1[n][1]));
            if (v1) lm = fmaxf(lm, fmaxf(c1[n][2], c1[n][3]));
        }
        #pragma unroll
        for (int off = 16; off; off >>= 1) lm = fmaxf(lm, __shfl_xor_sync(0xffffffffu, lm, off));
        if (lane == 0) ((float*)(smem + C_MX))[w] = lm;
        __syncthreads();
        float bmax = NEGINF;
        #pragma unroll
        for (int i = 0; i < 8; i++) bmax = fmaxf(bmax, ((float*)(smem + C_MX))[i]);
        float Mnew = fmaxf(Mold, bmax);

        if (wvalid) {
            float factor = __expf(Mold - Mnew);
            float f0 = (mr0 == MFEAT) ? 1.f : factor;
            float f1 = (mr0 + 8 == MFEAT) ? 1.f : factor;
            #pragma unroll
            for (int n = 0; n < 9; n++) {
                accC[n][0] *= f0; accC[n][1] *= f0;
                accC[n][2] *= f1; accC[n][3] *= f1;
            }

            // GEMM2: accC[m, e] += kpT @ w; A from registers (exp + C->A remap)
            float* dg = (float*)(smem + CD_);
            #pragma unroll
            for (int kt2 = 0; kt2 < 4; kt2++) {
                int u = 2 * kt2, vt = u + 1;
                int ncol = 16 * kt2 + qcol2;
                float dgu0 = dg[ncol],     dgu1 = dg[ncol + 1];
                float dgv0 = dg[ncol + 8], dgv1 = dg[ncol + 9];
                uint32_t qa_h[4], qa_l[4];
                {
                    float a0, a1, a2, a3;
                    if (mr0 < MFEAT) {
                        a0 = RATIO_C * __expf(c1[u][0] - dgu0 - Mnew);
                        a1 = RATIO_C * __expf(c1[u][1] - dgu1 - Mnew);
                        a2 = RATIO_C * __expf(c1[vt][0] - dgv0 - Mnew);
                        a3 = RATIO_C * __expf(c1[vt][1] - dgv1 - Mnew);
                    } else if (mr0 == MFEAT) { a0 = a1 = a2 = a3 = 1.f; }
                    else { a0 = a1 = a2 = a3 = 0.f; }
                    split2(a0, a1, qa_h[0], qa_l[0]);
                    split2(a2, a3, qa_h[2], qa_l[2]);
                }
                {
                    int m1 = mr0 + 8;
                    float a0, a1, a2, a3;
                    if (m1 < MFEAT) {
                        a0 = RATIO_C * __expf(c1[u][2] - dgu0 - Mnew);
                        a1 = RATIO_C * __expf(c1[u][3] - dgu1 - Mnew);
                        a2 = RATIO_C * __expf(c1[vt][2] - dgv0 - Mnew);
                        a3 = RATIO_C * __expf(c1[vt][3] - dgv1 - Mnew);
                    } else if (m1 == MFEAT) { a0 = a1 = a2 = a3 = 1.f; }
                    else { a0 = a1 = a2 = a3 = 0.f; }
                    split2(a0, a1, qa_h[1], qa_l[1]);
                    split2(a2, a3, qa_h[3], qa_l[3]);
                }
                uint32_t bwh[9][2], bwl[9][2];
                #pragma unroll
                for (int nE = 0; nE < 9; nE++) {
                    uint32_t b = sb + CW_H + (uint32_t)(kt2 * 16 + krb) * 176 + 16 * nE;
                    ldsm_x2t(bwh[nE], b);
                    ldsm_x2t(bwl[nE], b + (CW_L - CW_H));
                }
                #pragma unroll
                for (int nE = 0; nE < 9; nE++) {
                    mma_bf16(accC[nE], qa_h, bwh[nE]);
                    mma_bf16(accC[nE], qa_h, bwl[nE]);
                    mma_bf16(accC[nE], qa_l, bwh[nE]);
                }
            }
        }
        Mold = Mnew;
    }

    if (wvalid) {
        float* slab = g_ctxS + ((size_t)(ks * BH + bh)) * 72 * MP;
        #pragma unroll
        for (int nE = 0; nE < 9; nE++) {
            int e = 8 * nE + qcol2;
            slab[(size_t)e * MP + mr0]           = accC[nE][0];
            slab[(size_t)(e + 1) * MP + mr0]     = accC[nE][1];
            slab[(size_t)e * MP + mr0 + 8]       = accC[nE][2];
            slab[(size_t)(e + 1) * MP + mr0 + 8] = accC[nE][3];
        }
    }
    if (tid == 0) {
        g_ctxM[(ks * BH + bh) * 3 + mtile] = Mold;
        atomicMax(&g_kmax_enc, enc_f(Mold));
    }
}

// ---------------------------------------------------------------------------
// convert: merge slabs with e^{M_s,mt - G}; add analytic EPS; bf16 split; ctxsum.
// m rows >= 272 are never written by ctx -> guarded to zero here.
// ---------------------------------------------------------------------------
__global__ void __launch_bounds__(160) convert_kernel() {
    __shared__ float sc[KSPL * 3];
    __shared__ float vs_sh;
    __shared__ float red[5];
    int e = blockIdx.x, bh = blockIdx.y, t = threadIdx.x;
    float G = dec_f(g_kmax_enc);
    if (t < KSPL * 3) sc[t] = __expf(g_ctxM[(t / 3 * BH + bh) * 3 + (t % 3)] - G);
    if (t == 0) {
        float v = 0.f;
        #pragma unroll
        for (int ks = 0; ks < KSPL; ks++)
            v += g_ctxS[(((size_t)(ks * BH + bh)) * 72 + e) * MP + MFEAT];
        vs_sh = v;
    }
    __syncthreads();

    int mt = t >> 6;       // m = 2t: mtile = 2t/128 = t/64  (0,1,2)
    int m0 = 2 * t;
    float sx = 0.f, sy = 0.f;
    if (m0 < 272) {
        #pragma unroll
        for (int ks = 0; ks < KSPL; ks++) {
            float2 vv = *(const float2*)(g_ctxS + (((size_t)(ks * BH + bh)) * 72 + e) * MP + m0);
            float s = sc[ks * 3 + mt];
            sx += s * vv.x; sy += s * vv.y;
        }
    }
    float eps_add = REPS_C * vs_sh;
    float fx = (m0     < MFEAT) ? sx + eps_add : 0.f;
    float fy = (m0 + 1 < MFEAT) ? sy + eps_add : 0.f;
    uint32_t hi, lo; split2(fx, fy, hi, lo);
    g_cthp[((size_t)bh * 72 + e) * 160 + t] = hi;
    g_ctlp[((size_t)bh * 72 + e) * 160 + t] = lo;

    float part = fx + fy;
    #pragma unroll
    for (int off = 16; off; off >>= 1) part += __shfl_xor_sync(0xffffffffu, part, off);
    if ((t & 31) == 0) red[t >> 5] = part;
    __syncthreads();
    if (t == 0) g_ctxsum[bh * 72 + e] = red[0] + red[1] + red[2] + red[3] + red[4];
}

// ---------------------------------------------------------------------------
// out_fused: unchanged from R9 (passing, 169us).
// ---------------------------------------------------------------------------
#define OQ_H 0
#define OQ_L 18432
#define OP_H 36864
#define OP_L 46080
#define OC_H 55296
#define OC_L 65664
#define O_DG 76032
#define O_SZ 76544

__global__ void __launch_bounds__(256, 2) out_fused(const float* __restrict__ q_in,
                                                    const float* __restrict__ proj,
                                                    float* __restrict__ out) {
    extern __shared__ char smem[];
    uint32_t sb = smem_u32(smem);
    int tid = threadIdx.x, w = tid >> 5, lane = tid & 31;
    int bh = blockIdx.y, nt = blockIdx.x;
    const float* qb = q_in + ((size_t)bh * NSEQ + nt * 128) * DDIM;

    for (int i = tid; i < 128 * 32; i += 256) {
        int r = i >> 5, p = i & 31;
        float2 v = *(const float2*)(qb + r * 64 + 2 * p);
        uint32_t hi, lo; split2(DNORM * v.x, DNORM * v.y, hi, lo);
        *(uint32_t*)(smem + OQ_H + r * 144 + 4 * p) = hi;
        *(uint32_t*)(smem + OQ_L + r * 144 + 4 * p) = lo;
    }
    if (tid < 128) {
        float s = 0.f;
        #pragma unroll
        for (int d = 0; d < DDIM; d++) { float x = qb[tid * 64 + d]; s += x * x; }
        ((float*)(smem + O_DG))[tid] = 0.0625f * s;
    }
    __syncthreads();

    int arow = lane & 15, koff = (lane >> 4) * 16;
    int brow = lane & 7,  bk = ((lane >> 3) & 1) * 16;
    int qrow = lane >> 2, qcol2 = 2 * (lane & 3);
    int m0 = 16 * w;
    float dg0 = ((float*)(smem + O_DG))[m0 + qrow];
    float dg1 = ((float*)(smem + O_DG))[m0 + qrow + 8];
    float M0 = NEGINF, M1 = NEGINF;

    float accO[9][4];
    #pragma unroll
    for (int n = 0; n < 9; n++)
        #pragma unroll
        for (int x = 0; x < 4; x++) accO[n][x] = 0.f;

    #pragma unroll 1
    for (int ch = 0; ch < 5; ch++) {
        __syncthreads();
        for (int i = tid; i < 64 * 32; i += 256) {
            int r = i >> 5, p = i & 31;
            int m = ch * 64 + r;
            float2 v = (m < MFEAT) ? *(const float2*)(proj + m * 64 + 2 * p) : make_float2(0.f, 0.f);
            uint32_t hi, lo; split2(v.x, v.y, hi, lo);
            *(uint32_t*)(smem + OP_H + r * 144 + 4 * p) = hi;
            *(uint32_t*)(smem + OP_L + r * 144 + 4 * p) = lo;
        }
        for (int i = tid; i < 72 * 32; i += 256) {
            int e = i >> 5, p = i & 31;
            *(uint32_t*)(smem + OC_H + e * 144 + 4 * p) = g_cthp[((size_t)bh * 72 + e) * 160 + 32 * ch + p];
            *(uint32_t*)(smem + OC_L + e * 144 + 4 * p) = g_ctlp[((size_t)bh * 72 + e) * 160 + 32 * ch + p];
        }
        __syncthreads();

        float a1[8][4];
        #pragma unroll
        for (int n = 0; n < 8; n++)
            #pragma unroll
            for (int x = 0; x < 4; x++) a1[n][x] = 0.f;
        #pragma unroll
        for (int kt = 0; kt < 4; kt++) {
            uint32_t ah[4], al[4];
            uint32_t a = sb + OQ_H + (uint32_t)(m0 + arow) * 144 + kt * 32 + koff;
            ldsm_x4(ah, a);
            ldsm_x4(al, a + (OQ_L - OQ_H));
            uint32_t bh8[8][2], bl8[8][2];
            #pragma unroll
            for (int n = 0; n < 8; n++) {
                uint32_t b = sb + OP_H + (uint32_t)(8 * n + brow) * 144 + kt * 32 + bk;
                ldsm_x2(bh8[n], b);
                ldsm_x2(bl8[n], b + (OP_L - OP_H));
            }
            #pragma unroll
            for (int n = 0; n < 8; n++) {
                mma_bf16(a1[n], ah, bh8[n]);
                mma_bf16(a1[n], ah, bl8[n]);
                mma_bf16(a1[n], al, bh8[n]);
            }
        }

        float lm0 = NEGINF, lm1 = NEGINF;
        #pragma unroll
        for (int n = 0; n < 8; n++) {
            int gm = ch * 64 + 8 * n + qcol2;
            if (gm < MFEAT)     { lm0 = fmaxf(lm0, a1[n][0]); lm1 = fmaxf(lm1, a1[n][2]); }
            if (gm + 1 < MFEAT) { lm0 = fmaxf(lm0, a1[n][1]); lm1 = fmaxf(lm1, a1[n][3]); }
        }
        lm0 = fmaxf(lm0, __shfl_xor_sync(0xffffffffu, lm0, 1));
        lm0 = fmaxf(lm0, __shfl_xor_sync(0xffffffffu, lm0, 2));
        lm1 = fmaxf(lm1, __shfl_xor_sync(0xffffffffu, lm1, 1));
        lm1 = fmaxf(lm1, __shfl_xor_sync(0xffffffffu, lm1, 2));
        float Mn0 = fmaxf(M0, lm0), Mn1 = fmaxf(M1, lm1);
        float f0 = __expf(M0 - Mn0), f1 = __expf(M1 - Mn1);
        M0 = Mn0; M1 = Mn1;
        float off0 = dg0 + Mn0, off1 = dg1 + Mn1;
        #pragma unroll
        for (int n = 0; n < 9; n++) {
            accO[n][0] *= f0; accO[n][1] *= f0;
            accO[n][2] *= f1; accO[n][3] *= f1;
        }

        #pragma unroll
        for (int kt2 = 0; kt2 < 4; kt2++) {
            int u = 2 * kt2, vt = u + 1;
            int gmu = ch * 64 + 8 * u + qcol2;
            int gmv = gmu + 8;
            uint32_t qa_h[4], qa_l[4];
            {
                float a0 = (gmu     < MFEAT) ? RATIO_C * __expf(a1[u][0] - off0) : 0.f;
                float a1v = (gmu + 1 < MFEAT) ? RATIO_C * __expf(a1[u][1] - off0) : 0.f;
                float a2 = (gmv     < MFEAT) ? RATIO_C * __expf(a1[vt][0] - off0) : 0.f;
                float a3 = (gmv + 1 < MFEAT) ? RATIO_C * __expf(a1[vt][1] - off0) : 0.f;
                split2(a0, a1v, qa_h[0], qa_l[0]);
                split2(a2, a3, qa_h[2], qa_l[2]);
            }
            {
                float a0 = (gmu     < MFEAT) ? RATIO_C * __expf(a1[u][2] - off1) : 0.f;
                float a1v = (gmu + 1 < MFEAT) ? RATIO_C * __expf(a1[u][3] - off1) : 0.f;
                float a2 = (gmv     < MFEAT) ? RATIO_C * __expf(a1[vt][2] - off1) : 0.f;
                float a3 = (gmv + 1 < MFEAT) ? RATIO_C * __expf(a1[vt][3] - off1) : 0.f;
                split2(a0, a1v, qa_h[1], qa_l[1]);
                split2(a2, a3, qa_h[3], qa_l[3]);
            }
            uint32_t cbh[9][2], cbl[9][2];
            #pragma unroll
            for (int n = 0; n < 9; n++) {
                uint32_t b = sb + OC_H + (uint32_t)(8 * n + brow) * 144 + kt2 * 32 + bk;
                ldsm_x2(cbh[n], b);
                ldsm_x2(cbl[n], b + (OC_L - OC_H));
            }
            #pragma unroll
            for (int n = 0; n < 9; n++) {
                mma_bf16(accO[n], qa_h, cbh[n]);
                mma_bf16(accO[n], qa_h, cbl[n]);
                mma_bf16(accO[n], qa_l, cbh[n]);
            }
        }
    }

    #pragma unroll
    for (int n = 0; n < 9; n++) {
        int col = 8 * n + qcol2;
        float cs0 = g_ctxsum[bh * 72 + col];
        float cs1 = g_ctxsum[bh * 72 + col + 1];
        accO[n][0] += REPS_C * cs0; accO[n][1] += REPS_C * cs1;
        accO[n][2] += REPS_C * cs0; accO[n][3] += REPS_C * cs1;
    }
    float d0 = __shfl_sync(0xffffffffu, accO[8][0], lane & ~3);
    float d1 = __shfl_sync(0xffffffffu, accO[8][2], lane & ~3);
    float i0 = 1.0f / d0, i1 = 1.0f / d1;
    int r0g = nt * 128 + m0 + qrow;
    float* ob = out + (size_t)bh * NSEQ * DDIM;
    #pragma unroll
    for (int n = 0; n < 8; n++) {
        int col = 8 * n + qcol2;
        *(float2*)(ob + (size_t)r0g * DDIM + col) = make_float2(i0 * accO[n][0], i0 * accO[n][1]);
        *(float2*)(ob + (size_t)(r0g + 8) * DDIM + col) = make_float2(i1 * accO[n][2], i1 * accO[n][3]);
    }
}

// ---------------------------------------------------------------------------
extern "C" void kernel_launch(void* const* d_in, const int* in_sizes, int n_in,
                              void* d_out, int out_size) {
    const float* q    = (const float*)d_in[0];
    const float* k    = (const float*)d_in[1];
    const float* v    = (const float*)d_in[2];
    const float* proj = (const float*)d_in[3];
    float* out = (float*)d_out;

    cudaFuncSetAttribute(ctx_fused, cudaFuncAttributeMaxDynamicSharedMemorySize, CX_SZ);
    cudaFuncSetAttribute(out_fused, cudaFuncAttributeMaxDynamicSharedMemorySize, O_SZ);

    init_kernel<<<1, 32>>>();
    ctx_fused<<<dim3(3 * KSPL, BH), 256, CX_SZ>>>(k, v, proj);
    convert_kernel<<<dim3(72, BH), 160>>>();
    out_fused<<<dim3(NT, BH), 256, O_SZ>>>(q, proj, out);
}